// round 4
// baseline (speedup 1.0000x reference)
#include <cuda_runtime.h>
#include <math.h>
#include <math_constants.h>

#define Bn   8
#define Tn   128
#define U1n  33
#define Dn   512
#define Vn   4096
#define ROWS (Bn*Tn*U1n)   // 33792

#define BM 128
#define BN 64
#define BK 32

// Scratch: per-row statistics from the fused GEMM pass.
__device__ float g_lse[ROWS];
__device__ float g_blank[ROWS];
__device__ float g_tgt[ROWS];
__device__ float g_sum[ROWS];

// ---------------------------------------------------------------------------
// Kernel 1: fused logits GEMM + online logsumexp + pick blank/target + row sum
// grid = ROWS/BM = 264 blocks, 256 threads.
// Thread (ty,tx): ty=tid/16 owns 8 rows, tx=tid%16 owns 4 V-columns of chunk.
// ---------------------------------------------------------------------------
__global__ void __launch_bounds__(256) fused_gemm_stats(
    const float* __restrict__ x, const float* __restrict__ w,
    const float* __restrict__ bias, const int* __restrict__ targets)
{
    __shared__ __align__(16) float As[BK][BM + 4];  // transposed, padded
    __shared__ __align__(16) float Bs[BK][BN + 4];

    const int tid  = threadIdx.x;
    const int ty   = tid >> 4;      // 0..15
    const int tx   = tid & 15;      // 0..15
    const int row0 = blockIdx.x * BM;

    // per-row target vocab index (only lanes share per-ty rows; cheap redundancy)
    int vt8[8];
#pragma unroll
    for (int i = 0; i < 8; i++) {
        int r = row0 + ty * 8 + i;
        int u = r % U1n;
        int b = r / (Tn * U1n);
        vt8[i] = (u < U1n - 1) ? targets[b * (U1n - 1) + u] : -1;
    }

    float m_run[8], s_run[8], rowsum[8];
#pragma unroll
    for (int i = 0; i < 8; i++) { m_run[i] = -CUDART_INF_F; s_run[i] = 0.f; rowsum[i] = 0.f; }

    for (int vc = 0; vc < Vn; vc += BN) {
        float acc[8][4];
#pragma unroll
        for (int i = 0; i < 8; i++)
#pragma unroll
            for (int j = 0; j < 4; j++) acc[i][j] = 0.f;

        for (int k0 = 0; k0 < Dn; k0 += BK) {
            __syncthreads();
            // load x tile (128 rows x 32 k) -> As[k][row]
#pragma unroll
            for (int jj = 0; jj < 4; jj++) {
                int idx = tid + jj * 256;        // 0..1023
                int r   = idx >> 3;
                int c4  = idx & 7;
                float4 v = *reinterpret_cast<const float4*>(
                    x + (size_t)(row0 + r) * Dn + k0 + c4 * 4);
                As[c4 * 4 + 0][r] = v.x; As[c4 * 4 + 1][r] = v.y;
                As[c4 * 4 + 2][r] = v.z; As[c4 * 4 + 3][r] = v.w;
            }
            // load W tile (64 vocab rows x 32 k) -> Bs[k][col]
#pragma unroll
            for (int jj = 0; jj < 2; jj++) {
                int idx = tid + jj * 256;        // 0..511
                int r   = idx >> 3;
                int c4  = idx & 7;
                float4 v = *reinterpret_cast<const float4*>(
                    w + (size_t)(vc + r) * Dn + k0 + c4 * 4);
                Bs[c4 * 4 + 0][r] = v.x; Bs[c4 * 4 + 1][r] = v.y;
                Bs[c4 * 4 + 2][r] = v.z; Bs[c4 * 4 + 3][r] = v.w;
            }
            __syncthreads();
#pragma unroll
            for (int k = 0; k < BK; k++) {
                float4 a0 = *reinterpret_cast<const float4*>(&As[k][ty * 8]);
                float4 a1 = *reinterpret_cast<const float4*>(&As[k][ty * 8 + 4]);
                float4 b0 = *reinterpret_cast<const float4*>(&Bs[k][tx * 4]);
                float a[8] = {a0.x, a0.y, a0.z, a0.w, a1.x, a1.y, a1.z, a1.w};
                float bv[4] = {b0.x, b0.y, b0.z, b0.w};
#pragma unroll
                for (int i = 0; i < 8; i++)
#pragma unroll
                    for (int j = 0; j < 4; j++)
                        acc[i][j] = fmaf(a[i], bv[j], acc[i][j]);
            }
        }

        // bias + per-chunk statistics (online LSE over V)
        float bb0 = bias[vc + tx * 4 + 0];
        float bb1 = bias[vc + tx * 4 + 1];
        float bb2 = bias[vc + tx * 4 + 2];
        float bb3 = bias[vc + tx * 4 + 3];
#pragma unroll
        for (int i = 0; i < 8; i++) {
            float l0 = acc[i][0] + bb0, l1 = acc[i][1] + bb1;
            float l2 = acc[i][2] + bb2, l3 = acc[i][3] + bb3;
            int grow = row0 + ty * 8 + i;
            if (vc == 0 && tx == 0) g_blank[grow] = l0;   // vocab 0 = BLANK
            int lv = vt8[i] - vc - tx * 4;
            if (lv >= 0 && lv < 4) {
                float lt = (lv == 0) ? l0 : (lv == 1) ? l1 : (lv == 2) ? l2 : l3;
                g_tgt[grow] = lt;
            }
            rowsum[i] += (l0 + l1) + (l2 + l3);
            float m4 = fmaxf(fmaxf(l0, l1), fmaxf(l2, l3));
#pragma unroll
            for (int o = 8; o > 0; o >>= 1)
                m4 = fmaxf(m4, __shfl_xor_sync(0xffffffffu, m4, o, 16));
            float e = __expf(l0 - m4) + __expf(l1 - m4) + __expf(l2 - m4) + __expf(l3 - m4);
#pragma unroll
            for (int o = 8; o > 0; o >>= 1)
                e += __shfl_xor_sync(0xffffffffu, e, o, 16);
            float mnew = fmaxf(m_run[i], m4);
            s_run[i] = s_run[i] * __expf(m_run[i] - mnew) + e * __expf(m4 - mnew);
            m_run[i] = mnew;
        }
    }

#pragma unroll
    for (int i = 0; i < 8; i++) {
        float rs = rowsum[i];
#pragma unroll
        for (int o = 8; o > 0; o >>= 1)
            rs += __shfl_xor_sync(0xffffffffu, rs, o, 16);
        if (tx == 0) {
            int grow = row0 + ty * 8 + i;
            g_sum[grow] = rs;
            g_lse[grow] = m_run[i] + logf(s_run[i]);
        }
    }
}

// ---------------------------------------------------------------------------
// Kernel 2: RNN-T wavefront DP (warp per batch, lane = u) + label-smoothed CE
// ---------------------------------------------------------------------------
__device__ __forceinline__ float laddexp(float a, float b) {
    float m = fmaxf(a, b);
    return m + log1pf(__expf(-fabsf(a - b)));
}

__global__ void __launch_bounds__(256) finalize_kernel(
    const int* __restrict__ targets,
    const int* __restrict__ src_lengths,
    const int* __restrict__ tgt_lengths,
    float* __restrict__ out)
{
    __shared__ float red[256];
    __shared__ float batch_loss[8];
    const int tid  = threadIdx.x;
    const int warp = tid >> 5, lane = tid & 31;

    // ---- RNN-T forward DP on anti-diagonals ----
    {
        int b  = warp;                       // 8 warps, one per batch
        int S  = src_lengths[b];
        int TG = tgt_lengths[b];
        int base = b * Tn * U1n;
        float cur = 0.f;                     // alpha[t][u] for u = lane
        float cur2 = 0.f;                    // alpha[t][32] (lane 31 only)
        float afin = 0.f;
        bool have = false;
        int nsteps = (S - 1) + 32;
        for (int s = 0; s <= nsteps; s++) {
            float left   = __shfl_up_sync(0xffffffffu, cur, 1);  // alpha[t][u-1]
            float prev31 = cur;              // lane31: alpha[s-32][31]
            int t = s - lane;
            if (t >= 0 && t <= S - 1) {
                int u = lane;
                if (t == 0) {
                    if (u == 0) cur = 0.f;
                    else {
                        int rE = base + (u - 1);
                        cur = left + (g_tgt[rE] - g_lse[rE]);
                    }
                } else {
                    int rB = base + (t - 1) * U1n + u;
                    float up = cur + (g_blank[rB] - g_lse[rB]);
                    if (u == 0) cur = up;
                    else {
                        int rE = base + t * U1n + (u - 1);
                        cur = laddexp(up, left + (g_tgt[rE] - g_lse[rE]));
                    }
                }
                if (t == S - 1 && u == TG) { afin = cur; have = true; }
            }
            if (lane == 31) {                // extra column u = 32
                int t2 = s - 32;
                if (t2 >= 0 && t2 <= S - 1) {
                    int rE = base + t2 * U1n + 31;
                    float lft = prev31 + (g_tgt[rE] - g_lse[rE]);
                    if (t2 == 0) cur2 = lft;
                    else {
                        int rB = base + (t2 - 1) * U1n + 32;
                        cur2 = laddexp(cur2 + (g_blank[rB] - g_lse[rB]), lft);
                    }
                    if (t2 == S - 1 && TG == 32) { afin = cur2; have = true; }
                }
            }
        }
        float lossb = 0.f;
        if (have) {
            int rB = base + (S - 1) * U1n + TG;
            lossb = -(afin + (g_blank[rB] - g_lse[rB]));
        }
#pragma unroll
        for (int o = 16; o > 0; o >>= 1)
            lossb += __shfl_xor_sync(0xffffffffu, lossb, o);
        if (lane == 0) batch_loss[b] = lossb;
    }
    __syncthreads();

    // ---- label-smoothed CE at t = src_len-1, u = 0..31 ----
    float term;
    {
        int b = tid >> 5;
        int u = tid & 31;
        int S = src_lengths[b];
        int tv = targets[b * 32 + u];
        int row = b * Tn * U1n + (S - 1) * U1n + u;
        float lse = g_lse[row];
        float nll = lse - g_tgt[row];
        float smooth = (float)Vn * lse - g_sum[row];
        const float LS  = 0.1f;
        const float eps = LS / (float)(Vn - 1);
        float m = (tv != 1) ? 1.f : 0.f;   // PAD = 1
        term = ((1.f - LS - eps) * nll + eps * smooth) * m;
    }
    red[tid] = term;
    __syncthreads();
#pragma unroll
    for (int st = 128; st > 0; st >>= 1) {
        if (tid < st) red[tid] += red[tid + st];
        __syncthreads();
    }
    if (tid == 0) {
        float total = red[0];
#pragma unroll
        for (int b = 0; b < 8; b++) total += batch_loss[b];
        out[0] = total;
    }
}

// ---------------------------------------------------------------------------
extern "C" void kernel_launch(void* const* d_in, const int* in_sizes, int n_in,
                              void* d_out, int out_size)
{
    const float* x       = (const float*)d_in[0];
    const float* w       = (const float*)d_in[1];
    const float* bias    = (const float*)d_in[2];
    const int*   targets = (const int*)d_in[3];
    const int*   src     = (const int*)d_in[4];
    const int*   tgt     = (const int*)d_in[5];
    float* out = (float*)d_out;

    fused_gemm_stats<<<ROWS / BM, 256>>>(x, w, bias, targets);
    finalize_kernel<<<1, 256>>>(targets, src, tgt, out);
}

// round 6
// speedup vs baseline: 7.2128x; 7.2128x over previous
#include <cuda_runtime.h>
#include <cuda_bf16.h>
#include <math.h>
#include <stdint.h>

#define Bn   8
#define Tn   128
#define U1n  33
#define Dn   512
#define Vn   4096
#define BTU  (Tn*U1n)          // 4224
#define ROWS (Bn*BTU)          // 33792
#define MTL  (ROWS/128)        // 264 M-tiles
#define NVT  (Vn/128)          // 32 vocab tiles
#define NKC  (Dn/64)           // 8 k-chunks per vtile
#define NCH  (NVT*NKC)         // 256 chunks
#define L2E  1.442695040888963f

// smem layout (bytes)
#define SM_A     0u            // 128 x 512 bf16 = 131072
#define SM_B     131072u       // 2 stages x 16384 (128n x 64k bf16)
#define SM_BIAS  163840u       // 128 floats
#define SM_LSE   164352u       // 4 x 128 floats
#define SM_RAW   166400u       // 4 x 128 floats
#define SM_TOT   168448u

// ---------------- device scratch ----------------
__device__ __align__(16) __nv_bfloat16 g_Whi[(size_t)Vn*Dn];
__device__ float g_lse[ROWS];
__device__ float g_blank[ROWS];
__device__ float g_tgt[ROWS];
__device__ float g_sum[ROWS];
__device__ float g_part[Bn];

// ---------------- helpers ----------------
__device__ __forceinline__ uint32_t smem_u32(const void* p) {
    uint32_t a;
    asm("{ .reg .u64 t; cvta.to.shared.u64 t, %1; cvt.u32.u64 %0, t; }" : "=r"(a) : "l"(p));
    return a;
}
__device__ __forceinline__ void cpa16(uint32_t dst, const void* src) {
    asm volatile("cp.async.cg.shared.global [%0], [%1], 16;" :: "r"(dst), "l"(src));
}
// fast 2^z, FFMA-only (no MUFU). |rel err| ~2e-6 on the needed range.
__device__ __forceinline__ float exp2_fast(float z) {
    float zc = z + 12582912.f;              // round-to-nearest via magic
    int   ni = __float_as_int(zc);
    float n  = zc - 12582912.f;
    float f  = z - n;                        // f in [-0.5, 0.5]
    float p  = fmaf(0.0013333558f, f, 0.0096181291f);
    p = fmaf(p, f, 0.0555041087f);
    p = fmaf(p, f, 0.2402265069f);
    p = fmaf(p, f, 0.6931471806f);
    p = fmaf(p, f, 1.0f);
    return __int_as_float(__float_as_int(p) + (ni << 23));
}

// ---------------------------------------------------------------------------
// Kernel 0: convert W fp32 -> bf16 (hi)
// ---------------------------------------------------------------------------
__global__ void __launch_bounds__(256) convW_kernel(const float* __restrict__ w)
{
    int i = blockIdx.x * 256 + threadIdx.x;          // each handles 8 floats
    const float4* src = reinterpret_cast<const float4*>(w) + (size_t)i * 2;
    float4 v0 = src[0], v1 = src[1];
    __nv_bfloat162 p0 = __floats2bfloat162_rn(v0.x, v0.y);
    __nv_bfloat162 p1 = __floats2bfloat162_rn(v0.z, v0.w);
    __nv_bfloat162 p2 = __floats2bfloat162_rn(v1.x, v1.y);
    __nv_bfloat162 p3 = __floats2bfloat162_rn(v1.z, v1.w);
    uint4 o;
    o.x = *reinterpret_cast<uint32_t*>(&p0);
    o.y = *reinterpret_cast<uint32_t*>(&p1);
    o.z = *reinterpret_cast<uint32_t*>(&p2);
    o.w = *reinterpret_cast<uint32_t*>(&p3);
    *reinterpret_cast<uint4*>(g_Whi + (size_t)i * 8) = o;
}

// ---------------------------------------------------------------------------
// Kernel 1: bf16 mma.sync GEMM (A resident in smem) + fused statistics
//   grid = 264 blocks x 256 threads (8 warps: 2 m x 4 n), warp tile 64x32
// ---------------------------------------------------------------------------
extern __shared__ char dynsm[];

__global__ void __launch_bounds__(256, 1) maingemm_kernel(
    const float* __restrict__ x, const float* __restrict__ bias,
    const int* __restrict__ targets)
{
    const int tid  = threadIdx.x;
    const int lane = tid & 31;
    const int w    = tid >> 5;
    const int wm   = w >> 2;          // 0..1  (64 rows each)
    const int wn   = w & 3;           // 0..3  (32 cols each)
    const int row0 = blockIdx.x * 128;

    const uint32_t sb = smem_u32(dynsm);
    const uint32_t As = sb + SM_A;
    const uint32_t Bs = sb + SM_B;
    float* sbias = (float*)(dynsm + SM_BIAS);
    float* lseb  = (float*)(dynsm + SM_LSE);
    float* rawb  = (float*)(dynsm + SM_RAW);

    // ---- fill A: fp32 -> bf16 into swizzled smem (rows of 1KB, 16B chunks) ----
#pragma unroll 4
    for (int it = 0; it < 32; it++) {
        int idx = tid + it * 256;
        int r = idx >> 6, ch = idx & 63;
        const float4* src = reinterpret_cast<const float4*>(
            x + (size_t)(row0 + r) * Dn + ch * 8);
        float4 v0 = src[0], v1 = src[1];
        __nv_bfloat162 p0 = __floats2bfloat162_rn(v0.x, v0.y);
        __nv_bfloat162 p1 = __floats2bfloat162_rn(v0.z, v0.w);
        __nv_bfloat162 p2 = __floats2bfloat162_rn(v1.x, v1.y);
        __nv_bfloat162 p3 = __floats2bfloat162_rn(v1.z, v1.w);
        uint32_t dchunk = (uint32_t)((ch & ~7) | ((ch ^ r) & 7));
        uint32_t dst = As + r * 1024 + dchunk * 16;
        asm volatile("st.shared.v4.b32 [%0], {%1,%2,%3,%4};" ::
            "r"(dst),
            "r"(*reinterpret_cast<uint32_t*>(&p0)), "r"(*reinterpret_cast<uint32_t*>(&p1)),
            "r"(*reinterpret_cast<uint32_t*>(&p2)), "r"(*reinterpret_cast<uint32_t*>(&p3))
            : "memory");
    }

    // ---- per-lane ldmatrix bases ----
    const int arow = wm * 64 + (lane & 15);
    const uint32_t aBase = As + arow * 1024;
    const int alow = lane >> 4;                 // k-halfchunk select
    const int arx  = arow & 7;
    const int bn   = wn * 32 + ((lane >> 4) << 3) + (lane & 7);
    const int bko  = (lane >> 3) & 1;
    const int bnx  = bn & 7;

    // ---- per-thread row ids + target selectors ----
    int grow[8]; int tkey[8]; int tlo[8];
#pragma unroll
    for (int i = 0; i < 8; i++) {
        int mt = i >> 1, h = i & 1;
        int gr = row0 + wm * 64 + mt * 16 + (lane >> 2) + h * 8;
        grow[i] = gr;
        int b = gr / BTU, rem = gr % BTU, u = rem % U1n;
        int tv = (u < U1n - 1) ? targets[b * (U1n - 1) + u] : -1;
        int key = -1, lo = 0;
        if (tv >= 0 && ((tv >> 5) & 3) == wn && (((tv >> 1) & 3) == (lane & 3))) {
            key = tv >> 3;          // vt*16 + wn*4 + nt
            lo  = tv & 1;
        }
        tkey[i] = key; tlo[i] = lo;
    }
    const bool blankown = (wn == 0) && ((lane & 3) == 0);

    float acc[4][4][4];
#pragma unroll
    for (int a0 = 0; a0 < 4; a0++)
#pragma unroll
        for (int b0 = 0; b0 < 4; b0++)
#pragma unroll
            for (int c0 = 0; c0 < 4; c0++) acc[a0][b0][c0] = 0.f;
    float accE = 0.f, accR = 0.f;

    // ---- preload B chunk 0 ----
    {
        const __nv_bfloat16* wsrc = g_Whi;
#pragma unroll
        for (int it = 0; it < 4; it++) {
            int idx = tid + it * 256;
            int n = idx >> 3, cc = idx & 7;
            cpa16(Bs + n * 128 + ((cc ^ (n & 7))) * 16, wsrc + (size_t)n * Dn + cc * 8);
        }
        asm volatile("cp.async.commit_group;" ::: "memory");
    }

    for (int c = 0; c < NCH; c++) {
        const int vt = c >> 3, kc = c & 7, st = c & 1;
        __syncthreads();
        if (kc == 0 && tid < 128) sbias[tid] = bias[vt * 128 + tid];
        if (c + 1 < NCH) {
            const int c1 = c + 1;
            const __nv_bfloat16* wsrc = g_Whi + (size_t)(c1 >> 3) * 128 * Dn + (c1 & 7) * 64;
            const uint32_t dstb = Bs + ((c1 & 1) ? 16384u : 0u);
#pragma unroll
            for (int it = 0; it < 4; it++) {
                int idx = tid + it * 256;
                int n = idx >> 3, cc = idx & 7;
                cpa16(dstb + n * 128 + ((cc ^ (n & 7))) * 16, wsrc + (size_t)n * Dn + cc * 8);
            }
            asm volatile("cp.async.commit_group;" ::: "memory");
            asm volatile("cp.async.wait_group 1;" ::: "memory");
        } else {
            asm volatile("cp.async.wait_group 0;" ::: "memory");
        }
        __syncthreads();

        const uint32_t aCh = aBase + kc * 128;
        const uint32_t bSt = Bs + st * 16384 + bn * 128;
#pragma unroll
        for (int ks = 0; ks < 4; ks++) {
            uint32_t afr[4][4];
#pragma unroll
            for (int mt = 0; mt < 4; mt++) {
                uint32_t ad = aCh + mt * 16384 + (uint32_t)(((ks * 2 + alow) ^ arx)) * 16;
                asm volatile("ldmatrix.sync.aligned.m8n8.x4.shared.b16 {%0,%1,%2,%3}, [%4];"
                    : "=r"(afr[mt][0]), "=r"(afr[mt][1]), "=r"(afr[mt][2]), "=r"(afr[mt][3])
                    : "r"(ad));
            }
            uint32_t bfr[2][4];
#pragma unroll
            for (int np = 0; np < 2; np++) {
                uint32_t bd = bSt + np * 2048 + (uint32_t)(((ks * 2 + bko) ^ bnx)) * 16;
                asm volatile("ldmatrix.sync.aligned.m8n8.x4.shared.b16 {%0,%1,%2,%3}, [%4];"
                    : "=r"(bfr[np][0]), "=r"(bfr[np][1]), "=r"(bfr[np][2]), "=r"(bfr[np][3])
                    : "r"(bd));
            }
#pragma unroll
            for (int mt = 0; mt < 4; mt++)
#pragma unroll
                for (int nt = 0; nt < 4; nt++) {
                    asm volatile("mma.sync.aligned.m16n8k16.row.col.f32.bf16.bf16.f32 "
                        "{%0,%1,%2,%3}, {%4,%5,%6,%7}, {%8,%9}, {%0,%1,%2,%3};"
                        : "+f"(acc[mt][nt][0]), "+f"(acc[mt][nt][1]),
                          "+f"(acc[mt][nt][2]), "+f"(acc[mt][nt][3])
                        : "r"(afr[mt][0]), "r"(afr[mt][1]), "r"(afr[mt][2]), "r"(afr[mt][3]),
                          "r"(bfr[nt >> 1][(nt & 1) * 2]), "r"(bfr[nt >> 1][(nt & 1) * 2 + 1]));
                }
        }

        if (kc == 7) {
            // ---- epilogue for vtile vt ----
            float bcol[8];
#pragma unroll
            for (int nt = 0; nt < 4; nt++) {
                bcol[nt * 2]     = sbias[wn * 32 + nt * 8 + (lane & 3) * 2];
                bcol[nt * 2 + 1] = sbias[wn * 32 + nt * 8 + (lane & 3) * 2 + 1];
            }
            const int vbase = vt * 16 + wn * 4;
            float se[8], sr[8];
#pragma unroll
            for (int i = 0; i < 8; i++) { se[i] = 0.f; sr[i] = 0.f; }
#pragma unroll
            for (int mt = 0; mt < 4; mt++)
#pragma unroll
                for (int h = 0; h < 2; h++) {
                    const int i = mt * 2 + h;
#pragma unroll
                    for (int nt = 0; nt < 4; nt++)
#pragma unroll
                        for (int lo = 0; lo < 2; lo++) {
                            float y = acc[mt][nt][h * 2 + lo] + bcol[nt * 2 + lo];
                            sr[i] += y;
                            se[i] += exp2_fast(y * L2E);
                            if (tkey[i] == vbase + nt && tlo[i] == lo)
                                g_tgt[grow[i]] = y;
                            if (vt == 0 && nt == 0 && lo == 0 && blankown)
                                g_blank[grow[i]] = y;
                        }
                }
#pragma unroll
            for (int i = 0; i < 8; i++) {
                se[i] += __shfl_xor_sync(0xffffffffu, se[i], 1);
                se[i] += __shfl_xor_sync(0xffffffffu, se[i], 2);
                sr[i] += __shfl_xor_sync(0xffffffffu, sr[i], 1);
                sr[i] += __shfl_xor_sync(0xffffffffu, sr[i], 2);
            }
            if ((lane & 3) == 0) {
#pragma unroll
                for (int i = 0; i < 8; i++) {
                    int mt = i >> 1, h = i & 1;
                    int lr = wm * 64 + mt * 16 + (lane >> 2) + h * 8;
                    lseb[wn * 128 + lr] = se[i];
                    rawb[wn * 128 + lr] = sr[i];
                }
            }
            __syncthreads();
            if (tid < 128) {
                accE += (lseb[tid] + lseb[128 + tid]) + (lseb[256 + tid] + lseb[384 + tid]);
                accR += (rawb[tid] + rawb[128 + tid]) + (rawb[256 + tid] + rawb[384 + tid]);
            }
#pragma unroll
            for (int a0 = 0; a0 < 4; a0++)
#pragma unroll
                for (int b0 = 0; b0 < 4; b0++)
#pragma unroll
                    for (int c0 = 0; c0 < 4; c0++) acc[a0][b0][c0] = 0.f;
        }
    }

    if (tid < 128) {
        g_lse[row0 + tid] = logf(accE);
        g_sum[row0 + tid] = accR;
    }
}

// ---------------------------------------------------------------------------
// Kernel 2: per-batch DP (smem-staged) + label-smoothed CE  (8 blocks)
// ---------------------------------------------------------------------------
__device__ __forceinline__ float laddexp(float a, float b) {
    float m = fmaxf(a, b);
    return m + log1pf(__expf(-fabsf(a - b)));
}

__global__ void __launch_bounds__(256) finalize_kernel(
    const int* __restrict__ targets,
    const int* __restrict__ src_lengths,
    const int* __restrict__ tgt_lengths)
{
    __shared__ float sbl[BTU];
    __shared__ float sem[BTU];
    __shared__ float s_dp;
    const int b = blockIdx.x;
    const int tid = threadIdx.x;
    const int base = b * BTU;

    for (int i = tid; i < BTU; i += 256) {
        float l = g_lse[base + i];
        sbl[i] = g_blank[base + i] - l;
        sem[i] = g_tgt[base + i] - l;
    }
    __syncthreads();

    if (tid < 32) {
        const int lane = tid;
        const int S  = src_lengths[b];
        const int TG = tgt_lengths[b];
        float cur = 0.f, cur2 = 0.f, afin = 0.f;
        bool have = false;
        const int nsteps = (S - 1) + 32;
        for (int s = 0; s <= nsteps; s++) {
            float left   = __shfl_up_sync(0xffffffffu, cur, 1);
            float prev31 = cur;
            int t = s - lane;
            if (t >= 0 && t <= S - 1) {
                int u = lane;
                if (t == 0) {
                    cur = (u == 0) ? 0.f : left + sem[u - 1];
                } else {
                    float up = cur + sbl[(t - 1) * U1n + u];
                    cur = (u == 0) ? up : laddexp(up, left + sem[t * U1n + (u - 1)]);
                }
                if (t == S - 1 && u == TG) { afin = cur; have = true; }
            }
            if (lane == 31) {
                int t2 = s - 32;
                if (t2 >= 0 && t2 <= S - 1) {
                    float lft = prev31 + sem[t2 * U1n + 31];
                    cur2 = (t2 == 0) ? lft : laddexp(cur2 + sbl[(t2 - 1) * U1n + 32], lft);
                    if (t2 == S - 1 && TG == 32) { afin = cur2; have = true; }
                }
            }
        }
        float lossb = have ? -(afin + sbl[(S - 1) * U1n + TG]) : 0.f;
#pragma unroll
        for (int o = 16; o > 0; o >>= 1)
            lossb += __shfl_xor_sync(0xffffffffu, lossb, o);
        if (lane == 0) s_dp = lossb;
    }
    __syncthreads();

    if (tid < 32) {
        const int u = tid;
        const int S = src_lengths[b];
        const int tv = targets[b * (U1n - 1) + u];
        const int row = b * BTU + (S - 1) * U1n + u;
        float lse = g_lse[row];
        float nll = lse - g_tgt[row];
        float smooth = (float)Vn * lse - g_sum[row];
        const float LS = 0.1f;
        const float eps = LS / (float)(Vn - 1);
        float m = (tv != 1) ? 1.f : 0.f;
        float term = ((1.f - LS - eps) * nll + eps * smooth) * m;
#pragma unroll
        for (int o = 16; o > 0; o >>= 1)
            term += __shfl_xor_sync(0xffffffffu, term, o);
        if (u == 0) g_part[b] = s_dp + term;
    }
}

__global__ void reduce_kernel(float* __restrict__ out)
{
    if (threadIdx.x == 0) {
        float s = 0.f;
#pragma unroll
        for (int b = 0; b < Bn; b++) s += g_part[b];
        out[0] = s;
    }
}

// ---------------------------------------------------------------------------
extern "C" void kernel_launch(void* const* d_in, const int* in_sizes, int n_in,
                              void* d_out, int out_size)
{
    const float* x       = (const float*)d_in[0];
    const float* wgt     = (const float*)d_in[1];
    const float* bias    = (const float*)d_in[2];
    const int*   targets = (const int*)d_in[3];
    const int*   src     = (const int*)d_in[4];
    const int*   tgt     = (const int*)d_in[5];
    float* out = (float*)d_out;

    static bool attr_set = false;
    if (!attr_set) {
        cudaFuncSetAttribute(maingemm_kernel,
                             cudaFuncAttributeMaxDynamicSharedMemorySize, SM_TOT);
        attr_set = true;
    }

    convW_kernel<<<(Vn * Dn / 8) / 256, 256>>>(wgt);
    maingemm_kernel<<<MTL, 256, SM_TOT>>>(x, bias, targets);
    finalize_kernel<<<Bn, 256>>>(targets, src, tgt);
    reduce_kernel<<<1, 32>>>(out);
}

// round 7
// speedup vs baseline: 7.2946x; 1.0113x over previous
#include <cuda_runtime.h>
#include <cuda_bf16.h>
#include <math.h>
#include <stdint.h>

#define Bn   8
#define Tn   128
#define U1n  33
#define Dn   512
#define Vn   4096
#define BTU  (Tn*U1n)          // 4224
#define ROWS (Bn*BTU)          // 33792
#define MTL  (ROWS/128)        // 264 M-tiles
#define NVT  (Vn/128)          // 32 vocab tiles
#define NCH  (NVT*8)           // 256 chunks (64-k each)
#define L2E  1.442695040888963f

// smem layout (bytes)
#define SM_A     0u            // 128 x 512 bf16 = 131072
#define SM_B     131072u       // 3 stages x 16384 (128n x 64k bf16)
#define SM_BIAS  180224u       // 4096 floats = 16384
#define SM_RED   196608u       // 2 x 512 floats = 4096
#define SM_TOT   200704u

// ---------------- device scratch ----------------
__device__ __align__(16) __nv_bfloat16 g_Whi[(size_t)Vn*Dn];
__device__ float g_lse[ROWS];
__device__ float g_blank[ROWS];
__device__ float g_tgt[ROWS];
__device__ float g_sum[ROWS];
__device__ float g_part[Bn];

// ---------------- helpers ----------------
__device__ __forceinline__ uint32_t smem_u32(const void* p) {
    uint32_t a;
    asm("{ .reg .u64 t; cvta.to.shared.u64 t, %1; cvt.u32.u64 %0, t; }" : "=r"(a) : "l"(p));
    return a;
}
__device__ __forceinline__ void cpa16(uint32_t dst, const void* src) {
    asm volatile("cp.async.cg.shared.global [%0], [%1], 16;" :: "r"(dst), "l"(src));
}
// fast 2^z, FFMA-only (no MUFU). |rel err| ~2e-6.
__device__ __forceinline__ float exp2_fast(float z) {
    float zc = z + 12582912.f;
    int   ni = __float_as_int(zc);
    float n  = zc - 12582912.f;
    float f  = z - n;
    float p  = fmaf(0.0013333558f, f, 0.0096181291f);
    p = fmaf(p, f, 0.0555041087f);
    p = fmaf(p, f, 0.2402265069f);
    p = fmaf(p, f, 0.6931471806f);
    p = fmaf(p, f, 1.0f);
    return __int_as_float(__float_as_int(p) + (ni << 23));
}

// ---------------------------------------------------------------------------
// Kernel 0: convert W fp32 -> bf16
// ---------------------------------------------------------------------------
__global__ void __launch_bounds__(256) convW_kernel(const float* __restrict__ w)
{
    int i = blockIdx.x * 256 + threadIdx.x;          // each handles 8 floats
    const float4* src = reinterpret_cast<const float4*>(w) + (size_t)i * 2;
    float4 v0 = src[0], v1 = src[1];
    __nv_bfloat162 p0 = __floats2bfloat162_rn(v0.x, v0.y);
    __nv_bfloat162 p1 = __floats2bfloat162_rn(v0.z, v0.w);
    __nv_bfloat162 p2 = __floats2bfloat162_rn(v1.x, v1.y);
    __nv_bfloat162 p3 = __floats2bfloat162_rn(v1.z, v1.w);
    uint4 o;
    o.x = *reinterpret_cast<uint32_t*>(&p0);
    o.y = *reinterpret_cast<uint32_t*>(&p1);
    o.z = *reinterpret_cast<uint32_t*>(&p2);
    o.w = *reinterpret_cast<uint32_t*>(&p3);
    *reinterpret_cast<uint4*>(g_Whi + (size_t)i * 8) = o;
}

// ---------------------------------------------------------------------------
// Kernel 1: bf16 mma.sync GEMM (A resident in smem) + fused statistics
//   264 blocks x 256 threads (8 warps: 2 m x 4 n), warp tile 64x32
// ---------------------------------------------------------------------------
extern __shared__ char dynsm[];

__device__ __forceinline__ void load_Bchunk(uint32_t Bs, int c, int tid)
{
    const __nv_bfloat16* wsrc = g_Whi + ((size_t)(c >> 3)) * 128 * Dn + (c & 7) * 64;
    const uint32_t dstb = Bs + (uint32_t)(c % 3) * 16384u;
#pragma unroll
    for (int it = 0; it < 4; it++) {
        int idx = tid + it * 256;
        int n = idx >> 3, cc = idx & 7;
        cpa16(dstb + n * 128 + ((cc ^ (n & 7))) * 16, wsrc + (size_t)n * Dn + cc * 8);
    }
}

__global__ void __launch_bounds__(256, 1) maingemm_kernel(
    const float* __restrict__ x, const float* __restrict__ bias,
    const int* __restrict__ targets)
{
    const int tid  = threadIdx.x;
    const int lane = tid & 31;
    const int w    = tid >> 5;
    const int wm   = w >> 2;          // 0..1  (64 rows each)
    const int wn   = w & 3;           // 0..3  (32 cols each)
    const int row0 = blockIdx.x * 128;

    const uint32_t sb = smem_u32(dynsm);
    const uint32_t As = sb + SM_A;
    const uint32_t Bs = sb + SM_B;
    float* sbias = (float*)(dynsm + SM_BIAS);
    float* lseb  = (float*)(dynsm + SM_RED);
    float* rawb  = (float*)(dynsm + SM_RED + 2048);

    // ---- prologue: B chunks 0,1 + full bias via cp.async ----
    {
        load_Bchunk(Bs, 0, tid);
        const uint32_t bdst = sb + SM_BIAS + (uint32_t)tid * 64u;
#pragma unroll
        for (int q = 0; q < 4; q++)
            cpa16(bdst + q * 16, bias + tid * 16 + q * 4);
        asm volatile("cp.async.commit_group;" ::: "memory");
        load_Bchunk(Bs, 1, tid);
        asm volatile("cp.async.commit_group;" ::: "memory");
    }

    // ---- fill A: fp32 -> bf16 into swizzled smem (1KB rows, 16B chunks) ----
#pragma unroll 4
    for (int it = 0; it < 32; it++) {
        int idx = tid + it * 256;
        int r = idx >> 6, ch = idx & 63;
        const float4* src = reinterpret_cast<const float4*>(
            x + (size_t)(row0 + r) * Dn + ch * 8);
        float4 v0 = src[0], v1 = src[1];
        __nv_bfloat162 p0 = __floats2bfloat162_rn(v0.x, v0.y);
        __nv_bfloat162 p1 = __floats2bfloat162_rn(v0.z, v0.w);
        __nv_bfloat162 p2 = __floats2bfloat162_rn(v1.x, v1.y);
        __nv_bfloat162 p3 = __floats2bfloat162_rn(v1.z, v1.w);
        uint32_t dchunk = (uint32_t)((ch & ~7) | ((ch ^ r) & 7));
        uint32_t dst = As + r * 1024 + dchunk * 16;
        asm volatile("st.shared.v4.b32 [%0], {%1,%2,%3,%4};" ::
            "r"(dst),
            "r"(*reinterpret_cast<uint32_t*>(&p0)), "r"(*reinterpret_cast<uint32_t*>(&p1)),
            "r"(*reinterpret_cast<uint32_t*>(&p2)), "r"(*reinterpret_cast<uint32_t*>(&p3))
            : "memory");
    }

    // ---- per-lane ldmatrix bases ----
    const int arow = wm * 64 + (lane & 15);
    const uint32_t aBase = As + arow * 1024;
    const int alow = lane >> 4;
    const int arx  = arow & 7;
    const int bn   = wn * 32 + ((lane >> 4) << 3) + (lane & 7);
    const int bko  = (lane >> 3) & 1;
    const int bnx  = bn & 7;

    // ---- per-thread row ids + target selectors ----
    int grow[8]; int tkey[8]; int tlo[8];
#pragma unroll
    for (int i = 0; i < 8; i++) {
        int mt = i >> 1, h = i & 1;
        int gr = row0 + wm * 64 + mt * 16 + (lane >> 2) + h * 8;
        grow[i] = gr;
        int b = gr / BTU, rem = gr % BTU, u = rem % U1n;
        int tv = (u < U1n - 1) ? targets[b * (U1n - 1) + u] : -1;
        int key = -1, lo = 0;
        if (tv >= 0 && ((tv >> 5) & 3) == wn && (((tv >> 1) & 3) == (lane & 3))) {
            key = tv >> 3;
            lo  = tv & 1;
        }
        tkey[i] = key; tlo[i] = lo;
    }
    const bool blankown = (wn == 0) && ((lane & 3) == 0);

    float acc[4][4][4];
#pragma unroll
    for (int a0 = 0; a0 < 4; a0++)
#pragma unroll
        for (int b0 = 0; b0 < 4; b0++)
#pragma unroll
            for (int c0 = 0; c0 < 4; c0++) acc[a0][b0][c0] = 0.f;
    float se[8], sr[8];
#pragma unroll
    for (int i = 0; i < 8; i++) { se[i] = 0.f; sr[i] = 0.f; }

    for (int c = 0; c < NCH; c++) {
        const int vt = c >> 3, kc = c & 7, st = c % 3;
        __syncthreads();                       // stage (c+2)%3 free
        if (c + 2 < NCH) {
            load_Bchunk(Bs, c + 2, tid);
            asm volatile("cp.async.commit_group;" ::: "memory");
            asm volatile("cp.async.wait_group 2;" ::: "memory");
        } else if (c + 1 < NCH) {
            asm volatile("cp.async.wait_group 1;" ::: "memory");
        } else {
            asm volatile("cp.async.wait_group 0;" ::: "memory");
        }
        __syncthreads();                       // chunk c visible

        const uint32_t aCh = aBase + kc * 128;
        const uint32_t bSt = Bs + (uint32_t)st * 16384u + bn * 128;
#pragma unroll
        for (int ks = 0; ks < 4; ks++) {
            uint32_t afr[4][4];
#pragma unroll
            for (int mt = 0; mt < 4; mt++) {
                uint32_t ad = aCh + mt * 16384 + (uint32_t)(((ks * 2 + alow) ^ arx)) * 16;
                asm volatile("ldmatrix.sync.aligned.m8n8.x4.shared.b16 {%0,%1,%2,%3}, [%4];"
                    : "=r"(afr[mt][0]), "=r"(afr[mt][1]), "=r"(afr[mt][2]), "=r"(afr[mt][3])
                    : "r"(ad));
            }
            uint32_t bfr[2][4];
#pragma unroll
            for (int np = 0; np < 2; np++) {
                uint32_t bd = bSt + np * 2048 + (uint32_t)(((ks * 2 + bko) ^ bnx)) * 16;
                asm volatile("ldmatrix.sync.aligned.m8n8.x4.shared.b16 {%0,%1,%2,%3}, [%4];"
                    : "=r"(bfr[np][0]), "=r"(bfr[np][1]), "=r"(bfr[np][2]), "=r"(bfr[np][3])
                    : "r"(bd));
            }
#pragma unroll
            for (int mt = 0; mt < 4; mt++)
#pragma unroll
                for (int nt = 0; nt < 4; nt++) {
                    asm volatile("mma.sync.aligned.m16n8k16.row.col.f32.bf16.bf16.f32 "
                        "{%0,%1,%2,%3}, {%4,%5,%6,%7}, {%8,%9}, {%0,%1,%2,%3};"
                        : "+f"(acc[mt][nt][0]), "+f"(acc[mt][nt][1]),
                          "+f"(acc[mt][nt][2]), "+f"(acc[mt][nt][3])
                        : "r"(afr[mt][0]), "r"(afr[mt][1]), "r"(afr[mt][2]), "r"(afr[mt][3]),
                          "r"(bfr[nt >> 1][(nt & 1) * 2]), "r"(bfr[nt >> 1][(nt & 1) * 2 + 1]));
                }
        }

        if (kc == 7) {
            // ---- register-only epilogue for vtile vt ----
            float bcol[8];
#pragma unroll
            for (int nt = 0; nt < 4; nt++) {
                bcol[nt * 2]     = sbias[vt * 128 + wn * 32 + nt * 8 + (lane & 3) * 2];
                bcol[nt * 2 + 1] = sbias[vt * 128 + wn * 32 + nt * 8 + (lane & 3) * 2 + 1];
            }
            const int vbase = vt * 16 + wn * 4;
#pragma unroll
            for (int mt = 0; mt < 4; mt++)
#pragma unroll
                for (int h = 0; h < 2; h++) {
                    const int i = mt * 2 + h;
#pragma unroll
                    for (int nt = 0; nt < 4; nt++)
#pragma unroll
                        for (int lo = 0; lo < 2; lo++) {
                            float y = acc[mt][nt][h * 2 + lo] + bcol[nt * 2 + lo];
                            sr[i] += y;
                            se[i] += exp2_fast(y * L2E);
                            if (tkey[i] == vbase + nt && tlo[i] == lo)
                                g_tgt[grow[i]] = y;
                            if (vt == 0 && nt == 0 && lo == 0 && blankown)
                                g_blank[grow[i]] = y;
                        }
                }
#pragma unroll
            for (int a0 = 0; a0 < 4; a0++)
#pragma unroll
                for (int b0 = 0; b0 < 4; b0++)
#pragma unroll
                    for (int c0 = 0; c0 < 4; c0++) acc[a0][b0][c0] = 0.f;
        }
    }

    // ---- final cross-thread reduction (once) ----
#pragma unroll
    for (int i = 0; i < 8; i++) {
        se[i] += __shfl_xor_sync(0xffffffffu, se[i], 1);
        se[i] += __shfl_xor_sync(0xffffffffu, se[i], 2);
        sr[i] += __shfl_xor_sync(0xffffffffu, sr[i], 1);
        sr[i] += __shfl_xor_sync(0xffffffffu, sr[i], 2);
    }
    __syncthreads();
    if ((lane & 3) == 0) {
#pragma unroll
        for (int i = 0; i < 8; i++) {
            int mt = i >> 1, h = i & 1;
            int lr = wm * 64 + mt * 16 + (lane >> 2) + h * 8;
            lseb[wn * 128 + lr] = se[i];
            rawb[wn * 128 + lr] = sr[i];
        }
    }
    __syncthreads();
    if (tid < 128) {
        float E = (lseb[tid] + lseb[128 + tid]) + (lseb[256 + tid] + lseb[384 + tid]);
        float R = (rawb[tid] + rawb[128 + tid]) + (rawb[256 + tid] + rawb[384 + tid]);
        g_lse[row0 + tid] = logf(E);
        g_sum[row0 + tid] = R;
    }
}

// ---------------------------------------------------------------------------
// Kernel 2: per-batch DP (smem-staged) + label-smoothed CE  (8 blocks)
// ---------------------------------------------------------------------------
__device__ __forceinline__ float laddexp(float a, float b) {
    float m = fmaxf(a, b);
    return m + log1pf(__expf(-fabsf(a - b)));
}

__global__ void __launch_bounds__(256) finalize_kernel(
    const int* __restrict__ targets,
    const int* __restrict__ src_lengths,
    const int* __restrict__ tgt_lengths)
{
    __shared__ float sbl[BTU];
    __shared__ float sem[BTU];
    __shared__ float s_dp;
    const int b = blockIdx.x;
    const int tid = threadIdx.x;
    const int base = b * BTU;

    for (int i = tid; i < BTU; i += 256) {
        float l = g_lse[base + i];
        sbl[i] = g_blank[base + i] - l;
        sem[i] = g_tgt[base + i] - l;
    }
    __syncthreads();

    if (tid < 32) {
        const int lane = tid;
        const int S  = src_lengths[b];
        const int TG = tgt_lengths[b];
        float cur = 0.f, cur2 = 0.f, afin = 0.f;
        bool have = false;
        const int nsteps = (S - 1) + 32;
        for (int s = 0; s <= nsteps; s++) {
            float left   = __shfl_up_sync(0xffffffffu, cur, 1);
            float prev31 = cur;
            int t = s - lane;
            if (t >= 0 && t <= S - 1) {
                int u = lane;
                if (t == 0) {
                    cur = (u == 0) ? 0.f : left + sem[u - 1];
                } else {
                    float up = cur + sbl[(t - 1) * U1n + u];
                    cur = (u == 0) ? up : laddexp(up, left + sem[t * U1n + (u - 1)]);
                }
                if (t == S - 1 && u == TG) { afin = cur; have = true; }
            }
            if (lane == 31) {
                int t2 = s - 32;
                if (t2 >= 0 && t2 <= S - 1) {
                    float lft = prev31 + sem[t2 * U1n + 31];
                    cur2 = (t2 == 0) ? lft : laddexp(cur2 + sbl[(t2 - 1) * U1n + 32], lft);
                    if (t2 == S - 1 && TG == 32) { afin = cur2; have = true; }
                }
            }
        }
        float lossb = have ? -(afin + sbl[(S - 1) * U1n + TG]) : 0.f;
#pragma unroll
        for (int o = 16; o > 0; o >>= 1)
            lossb += __shfl_xor_sync(0xffffffffu, lossb, o);
        if (lane == 0) s_dp = lossb;
    }
    __syncthreads();

    if (tid < 32) {
        const int u = tid;
        const int S = src_lengths[b];
        const int tv = targets[b * (U1n - 1) + u];
        const int row = b * BTU + (S - 1) * U1n + u;
        float lse = g_lse[row];
        float nll = lse - g_tgt[row];
        float smooth = (float)Vn * lse - g_sum[row];
        const float LS = 0.1f;
        const float eps = LS / (float)(Vn - 1);
        float m = (tv != 1) ? 1.f : 0.f;
        float term = ((1.f - LS - eps) * nll + eps * smooth) * m;
#pragma unroll
        for (int o = 16; o > 0; o >>= 1)
            term += __shfl_xor_sync(0xffffffffu, term, o);
        if (u == 0) g_part[b] = s_dp + term;
    }
}

__global__ void reduce_kernel(float* __restrict__ out)
{
    if (threadIdx.x == 0) {
        float s = 0.f;
#pragma unroll
        for (int b = 0; b < Bn; b++) s += g_part[b];
        out[0] = s;
    }
}

// ---------------------------------------------------------------------------
extern "C" void kernel_launch(void* const* d_in, const int* in_sizes, int n_in,
                              void* d_out, int out_size)
{
    const float* x       = (const float*)d_in[0];
    const float* wgt     = (const float*)d_in[1];
    const float* bias    = (const float*)d_in[2];
    const int*   targets = (const int*)d_in[3];
    const int*   src     = (const int*)d_in[4];
    const int*   tgt     = (const int*)d_in[5];
    float* out = (float*)d_out;

    static bool attr_set = false;
    if (!attr_set) {
        cudaFuncSetAttribute(maingemm_kernel,
                             cudaFuncAttributeMaxDynamicSharedMemorySize, SM_TOT);
        attr_set = true;
    }

    convW_kernel<<<(Vn * Dn / 8) / 256, 256>>>(wgt);
    maingemm_kernel<<<MTL, 256, SM_TOT>>>(x, bias, targets);
    finalize_kernel<<<Bn, 256>>>(targets, src, tgt);
    reduce_kernel<<<1, 32>>>(out);
}